// round 2
// baseline (speedup 1.0000x reference)
#include <cuda_runtime.h>

// NEAT feed-forward DAG evaluator.
// Shapes (fixed by the problem): x[4096,512] f32, W[1536,2048] f32 strictly
// lower triangular (row i nonzero only for col < 512+i), b[1536], out[4096,256].
//
// Strategy: each CTA owns BR=16 batch rows; the full 2048-wide activation
// vector per row lives in SMEM. Nodes are processed in chunks of CC=64:
//   phase 1: dense panel GEMM  Z[16,64] += Out[16, 0:g0] @ W_chunk^T
//            (register-tiled 2x4 micro-kernel, split-K across 2 thread halves,
//             W staged k-major with XOR swizzle, register-pipelined prefetch)
//   phase 2: sequential 64x64 triangle, one thread per batch row,
//            float4 dot + sigmoid, writing new activations back to SMEM.
// Rows are independent -> no inter-CTA sync anywhere.

#define NTHREADS 256
#define BR 16
#define CC 64
#define NIN 512
#define NEVAL 1536
#define NN 2048
#define NOUT 256
#define NCHUNK (NEVAL / CC)          // 24
#define SO 2052                      // outS row stride (floats), pad vs 2048
#define WR 68                        // wS/wD row stride (floats)
#define ZR 66                        // zS row stride (floats)

#define SMEM_FLOATS (BR * SO + CC * WR + CC * WR + 2 * BR * ZR)
#define SMEM_BYTES (SMEM_FLOATS * 4)

__device__ __forceinline__ int ws_idx(int k, int c) {
    // k-major storage with XOR swizzle on the node index (keeps float4 groups
    // of 4 consecutive c intact; makes both STS (stage) and LDS.128 (gemm)
    // conflict-free).
    return k * WR + (c ^ ((k & 7) << 2));
}

__global__ void __launch_bounds__(NTHREADS, 1)
neat_ff_kernel(const float* __restrict__ x,
               const float* __restrict__ W,
               const float* __restrict__ bias,
               float* __restrict__ out)
{
    extern __shared__ float smem[];
    float* outS = smem;                 // [BR][SO]  activations (x + evaluated)
    float* wS   = outS + BR * SO;       // [CC k][WR] swizzled, phase-1 GEMM
    float* wD   = wS + CC * WR;         // [CC c][WR] plain c-major, diagonal blk
    float* zS   = wD + CC * WR;         // [2 tz][BR][ZR] partial sums

    const int tid  = threadIdx.x;
    const int row0 = blockIdx.x * BR;

    // ---- load x tile into outS[:, 0:NIN] (float4, coalesced) ----
    for (int i = tid; i < BR * (NIN / 4); i += NTHREADS) {
        int r = i >> 7;          // / (NIN/4)
        int q = i & 127;
        float4 v = *(const float4*)&x[(row0 + r) * NIN + 4 * q];
        *(float4*)&outS[r * SO + 4 * q] = v;
    }

    // GEMM thread mapping: 2 split-K halves x 8 row-pairs x 16 col-quads
    const int tz = tid >> 7;            // 0..1  (k half)
    const int rp = (tid >> 4) & 7;      // 0..7  (rows 2rp, 2rp+1)
    const int cq = tid & 15;            // 0..15 (cols 4cq .. 4cq+3)
    const int r0 = 2 * rp;
    const int c0 = 4 * cq;

    // staging map: each thread moves 4 float4s of a 64x64 W block
    float4 v[4];
    int sc[4], sq[4];
    #pragma unroll
    for (int p = 0; p < 4; p++) {
        int lin = p * NTHREADS + tid;   // 0..1023
        sc[p] = lin >> 4;               // node-in-chunk 0..63
        sq[p] = lin & 15;               // float4 index over k
    }

    // prefetch first W block (chunk 0, kb 0) into registers
    #pragma unroll
    for (int p = 0; p < 4; p++)
        v[p] = *(const float4*)&W[sc[p] * NN + 4 * sq[p]];

    for (int ch = 0; ch < NCHUNK; ch++) {
        const int i0 = ch * CC;         // first evaluated node of this chunk
        const int g0 = NIN + i0;        // its global column index

        float acc[2][4];
        #pragma unroll
        for (int a = 0; a < 2; a++)
            #pragma unroll
            for (int c = 0; c < 4; c++)
                acc[a][c] = 0.0f;

        // ---- phase 1: panel GEMM over all columns < g0 ----
        for (int kb = 0; kb < g0; kb += CC) {
            __syncthreads();            // protect wS readers of prev block
            // commit prefetched block (i0, kb) -> wS, k-major + swizzle
            #pragma unroll
            for (int p = 0; p < 4; p++) {
                int k = 4 * sq[p];
                int c = sc[p];
                wS[ws_idx(k + 0, c)] = v[p].x;
                wS[ws_idx(k + 1, c)] = v[p].y;
                wS[ws_idx(k + 2, c)] = v[p].z;
                wS[ws_idx(k + 3, c)] = v[p].w;
            }
            __syncthreads();
            // prefetch next block; when kb+CC == g0 this is the diagonal block
            {
                int nkb = kb + CC;
                #pragma unroll
                for (int p = 0; p < 4; p++)
                    v[p] = *(const float4*)&W[(i0 + sc[p]) * NN + nkb + 4 * sq[p]];
            }
            // 2x4 register micro-tile, vectorized by 4 over k
            const float* orow0 = &outS[r0 * SO + kb];
            const float* orow1 = orow0 + SO;
            #pragma unroll
            for (int k4 = 0; k4 < 8; k4++) {
                int kk = tz * 32 + k4 * 4;
                float4 a0 = *(const float4*)&orow0[kk];
                float4 a1 = *(const float4*)&orow1[kk];
                float4 w0 = *(const float4*)&wS[(kk + 0) * WR + (c0 ^ (((kk + 0) & 7) << 2))];
                float4 w1 = *(const float4*)&wS[(kk + 1) * WR + (c0 ^ (((kk + 1) & 7) << 2))];
                float4 w2 = *(const float4*)&wS[(kk + 2) * WR + (c0 ^ (((kk + 2) & 7) << 2))];
                float4 w3 = *(const float4*)&wS[(kk + 3) * WR + (c0 ^ (((kk + 3) & 7) << 2))];
                float av0[4] = {a0.x, a0.y, a0.z, a0.w};
                float av1[4] = {a1.x, a1.y, a1.z, a1.w};
                float wv[4][4] = {{w0.x, w0.y, w0.z, w0.w},
                                  {w1.x, w1.y, w1.z, w1.w},
                                  {w2.x, w2.y, w2.z, w2.w},
                                  {w3.x, w3.y, w3.z, w3.w}};
                #pragma unroll
                for (int e = 0; e < 4; e++)
                    #pragma unroll
                    for (int c = 0; c < 4; c++) {
                        acc[0][c] = fmaf(av0[e], wv[e][c], acc[0][c]);
                        acc[1][c] = fmaf(av1[e], wv[e][c], acc[1][c]);
                    }
            }
        }

        // ---- phase 2 setup: v holds the diagonal block (i0, g0) ----
        __syncthreads();
        // commit diagonal block plain c-major into wD (serial reads rows of W)
        #pragma unroll
        for (int p = 0; p < 4; p++)
            *(float4*)&wD[sc[p] * WR + 4 * sq[p]] = v[p];
        // write split-K partial sums
        #pragma unroll
        for (int a = 0; a < 2; a++)
            #pragma unroll
            for (int c = 0; c < 4; c++)
                zS[tz * (BR * ZR) + (r0 + a) * ZR + (c0 + c)] = acc[a][c];
        // prefetch first block of next chunk (overlaps the serial phase)
        if (ch + 1 < NCHUNK) {
            #pragma unroll
            for (int p = 0; p < 4; p++)
                v[p] = *(const float4*)&W[(i0 + CC + sc[p]) * NN + 4 * sq[p]];
        }
        __syncthreads();

        // ---- phase 2: sequential 64-node triangle, one thread per row ----
        if (tid < BR) {
            const int r = tid;
            float* orow = &outS[r * SO];
            #pragma unroll 1
            for (int k = 0; k < CC; k++) {
                float z = zS[r * ZR + k] + zS[BR * ZR + r * ZR + k]
                        + __ldg(&bias[i0 + k]);
                float s0 = 0.f, s1 = 0.f, s2 = 0.f, s3 = 0.f;
                const float* wrow = &wD[k * WR];
                int kf = k & ~3;
                for (int j = 0; j < kf; j += 4) {
                    float4 o4 = *(const float4*)&orow[g0 + j];
                    float4 w4 = *(const float4*)&wrow[j];
                    s0 = fmaf(o4.x, w4.x, s0);
                    s1 = fmaf(o4.y, w4.y, s1);
                    s2 = fmaf(o4.z, w4.z, s2);
                    s3 = fmaf(o4.w, w4.w, s3);
                }
                for (int j = kf; j < k; j++)
                    s0 = fmaf(orow[g0 + j], wrow[j], s0);
                z += (s0 + s1) + (s2 + s3);
                float t = 5.0f * z;
                t = fminf(fmaxf(t, -60.0f), 60.0f);
                float o = 1.0f / (1.0f + __expf(-t));
                orow[g0 + k] = o;
            }
        }
        // next chunk's first __syncthreads makes the new activations visible
    }

    __syncthreads();
    // ---- write output: global columns NN-NOUT .. NN-1 ----
    for (int i = tid; i < BR * (NOUT / 4); i += NTHREADS) {
        int r = i >> 6;          // / (NOUT/4)
        int q = i & 63;
        float4 vv = *(const float4*)&outS[r * SO + (NN - NOUT) + 4 * q];
        *(float4*)&out[(row0 + r) * NOUT + 4 * q] = vv;
    }
}

extern "C" void kernel_launch(void* const* d_in, const int* in_sizes, int n_in,
                              void* d_out, int out_size) {
    const float* x    = (const float*)d_in[0];
    const float* W    = (const float*)d_in[1];
    const float* bias = (const float*)d_in[2];
    float* out        = (float*)d_out;
    (void)in_sizes; (void)n_in; (void)out_size;

    cudaFuncSetAttribute(neat_ff_kernel,
                         cudaFuncAttributeMaxDynamicSharedMemorySize,
                         SMEM_BYTES);
    neat_ff_kernel<<<4096 / BR, NTHREADS, SMEM_BYTES>>>(x, W, bias, out);
}

// round 3
// speedup vs baseline: 3.0988x; 3.0988x over previous
#include <cuda_runtime.h>

// NEAT feed-forward DAG evaluator — R3.
// x[4096,512] f32, W[1536,2048] f32 strictly lower-tri, b[1536], out[4096,256].
//
// Per CTA: BR=16 batch rows, full 2048-wide activation tile in SMEM.
// Per chunk of CC=64 nodes:
//   phase 1: panel GEMM Z[16,64] += Out[16,0:g0] @ W_chunk^T
//            512 threads, split-K=8 x (4 rows x 4 cols)/thread micro-tile,
//            W staged k-major with pi(k)=k+(k>>2) row interleave
//            (conflict-free STS transpose AND conflict-free LDS reads).
//   phase 2: 64-node triangle, ONE WARP PER BATCH ROW (16 warps busy):
//            64 accumulators live 2-per-lane; each step broadcasts the new
//            node's z via shfl, applies sigmoid, rank-1 updates the rest.

#define NTHREADS 512
#define BR 16
#define CC 64
#define NIN 512
#define NEVAL 1536
#define NN 2048
#define NOUT 256
#define NCHUNK (NEVAL / CC)      // 24
#define SO 2052                  // outS row stride (floats)
#define WSR 68                   // wS row stride
#define WSROWS 80                // pi(63)=78 -> 79 rows, padded
#define WDR 68                   // wDT row stride
#define ZR 68                    // zS/zR row stride

#define SMEM_FLOATS (BR*SO + WSROWS*WSR + CC*WDR + 8*BR*ZR + BR*ZR)
#define SMEM_BYTES (SMEM_FLOATS * 4)

__global__ void __launch_bounds__(NTHREADS, 1)
neat_ff_kernel(const float* __restrict__ x,
               const float* __restrict__ W,
               const float* __restrict__ bias,
               float* __restrict__ out)
{
    extern __shared__ float smem[];
    float* outS = smem;                    // [BR][SO]
    float* wS   = outS + BR * SO;          // [WSROWS][WSR] k-major, pi-interleaved
    float* wDT  = wS + WSROWS * WSR;       // [CC j][WDR]  transposed diagonal blk
    float* zS   = wDT + CC * WDR;          // [8 sp][BR][ZR] split-K partials
    float* zR   = zS + 8 * BR * ZR;        // [BR][ZR]       reduced partials

    const int tid  = threadIdx.x;
    const int row0 = blockIdx.x * BR;

    // ---- load x tile (float4, coalesced) ----
    for (int i = tid; i < BR * (NIN / 4); i += NTHREADS) {
        int r = i >> 7, q = i & 127;
        *(float4*)&outS[r * SO + 4 * q] = *(const float4*)&x[(row0 + r) * NIN + 4 * q];
    }

    // GEMM mapping: splitK sp (8 ks each) x rg (4 rows) x cg (4 cols)
    const int sp = tid >> 6;               // 0..7
    const int t6 = tid & 63;
    const int cg = t6 & 15;  const int c0 = 4 * cg;
    const int rg = t6 >> 4;  const int r0 = 4 * rg;

    // staging mapping: 64 nodes x 16 k-quads; warp = 4 sc x 8 sq -> coalesced
    const int ssc  = (tid >> 3) & 63;      // node within chunk
    const int ssq0 = tid & 7;              // k-quad (p=0); p=1 uses ssq0+8

    const int lane = tid & 31;
    const int wrp  = tid >> 5;             // 0..15 -> batch row in triangle

    // prefetch first W block (chunk 0, kb 0)
    float4 v0 = *(const float4*)&W[ssc * NN + 4 * ssq0];
    float4 v1 = *(const float4*)&W[ssc * NN + 4 * (ssq0 + 8)];

    for (int ch = 0; ch < NCHUNK; ch++) {
        const int i0 = ch * CC;
        const int g0 = NIN + i0;

        float4 acc[4];
        #pragma unroll
        for (int rr = 0; rr < 4; rr++) acc[rr] = make_float4(0.f, 0.f, 0.f, 0.f);

        // ---- phase 1: panel GEMM over columns < g0 ----
        for (int kb = 0; kb < g0; kb += CC) {
            __syncthreads();               // prev wS readers done
            // commit v -> wS: k = 4*sq + i at physical row 5*sq + i (pi interleave)
            {
                int b0 = 5 * ssq0;         // pi(4*ssq0)
                wS[(b0 + 0) * WSR + ssc] = v0.x;
                wS[(b0 + 1) * WSR + ssc] = v0.y;
                wS[(b0 + 2) * WSR + ssc] = v0.z;
                wS[(b0 + 3) * WSR + ssc] = v0.w;
                int b1 = b0 + 40;          // pi(4*(ssq0+8))
                wS[(b1 + 0) * WSR + ssc] = v1.x;
                wS[(b1 + 1) * WSR + ssc] = v1.y;
                wS[(b1 + 2) * WSR + ssc] = v1.z;
                wS[(b1 + 3) * WSR + ssc] = v1.w;
            }
            __syncthreads();
            // prefetch next block (diagonal block when nkb == g0)
            {
                int nkb = kb + CC;
                v0 = *(const float4*)&W[(i0 + ssc) * NN + nkb + 4 * ssq0];
                v1 = *(const float4*)&W[(i0 + ssc) * NN + nkb + 4 * (ssq0 + 8)];
            }
            // micro-kernel: 2 k-quads of this thread's split
            #pragma unroll
            for (int q = 0; q < 2; q++) {
                const int kk = sp * 8 + 4 * q;
                const int pb = kk + (kk >> 2);       // pi(kk), kk mult of 4
                float4 a0 = *(const float4*)&outS[(r0 + 0) * SO + kb + kk];
                float4 a1 = *(const float4*)&outS[(r0 + 1) * SO + kb + kk];
                float4 a2 = *(const float4*)&outS[(r0 + 2) * SO + kb + kk];
                float4 a3 = *(const float4*)&outS[(r0 + 3) * SO + kb + kk];
                float4 w0 = *(const float4*)&wS[(pb + 0) * WSR + c0];
                float4 w1 = *(const float4*)&wS[(pb + 1) * WSR + c0];
                float4 w2 = *(const float4*)&wS[(pb + 2) * WSR + c0];
                float4 w3 = *(const float4*)&wS[(pb + 3) * WSR + c0];
                #pragma unroll
                for (int rr = 0; rr < 4; rr++) {
                    float4 a = (rr == 0) ? a0 : (rr == 1) ? a1 : (rr == 2) ? a2 : a3;
                    acc[rr].x = fmaf(a.x, w0.x, acc[rr].x);
                    acc[rr].y = fmaf(a.x, w0.y, acc[rr].y);
                    acc[rr].z = fmaf(a.x, w0.z, acc[rr].z);
                    acc[rr].w = fmaf(a.x, w0.w, acc[rr].w);
                    acc[rr].x = fmaf(a.y, w1.x, acc[rr].x);
                    acc[rr].y = fmaf(a.y, w1.y, acc[rr].y);
                    acc[rr].z = fmaf(a.y, w1.z, acc[rr].z);
                    acc[rr].w = fmaf(a.y, w1.w, acc[rr].w);
                    acc[rr].x = fmaf(a.z, w2.x, acc[rr].x);
                    acc[rr].y = fmaf(a.z, w2.y, acc[rr].y);
                    acc[rr].z = fmaf(a.z, w2.z, acc[rr].z);
                    acc[rr].w = fmaf(a.z, w2.w, acc[rr].w);
                    acc[rr].x = fmaf(a.w, w3.x, acc[rr].x);
                    acc[rr].y = fmaf(a.w, w3.y, acc[rr].y);
                    acc[rr].z = fmaf(a.w, w3.z, acc[rr].z);
                    acc[rr].w = fmaf(a.w, w3.w, acc[rr].w);
                }
            }
        }

        __syncthreads();                   // GEMM reads done
        // split-K partials -> zS (float4, conflict-free)
        #pragma unroll
        for (int rr = 0; rr < 4; rr++)
            *(float4*)&zS[(sp * BR + r0 + rr) * ZR + c0] = acc[rr];
        // diagonal block (in v) -> wDT transposed: wDT[j][node], j = 4*sq + i
        {
            int j0 = 4 * ssq0;
            wDT[(j0 + 0) * WDR + ssc] = v0.x;
            wDT[(j0 + 1) * WDR + ssc] = v0.y;
            wDT[(j0 + 2) * WDR + ssc] = v0.z;
            wDT[(j0 + 3) * WDR + ssc] = v0.w;
            int j1 = j0 + 32;
            wDT[(j1 + 0) * WDR + ssc] = v1.x;
            wDT[(j1 + 1) * WDR + ssc] = v1.y;
            wDT[(j1 + 2) * WDR + ssc] = v1.z;
            wDT[(j1 + 3) * WDR + ssc] = v1.w;
        }
        // prefetch first block of next chunk (overlaps reduce + triangle)
        if (ch + 1 < NCHUNK) {
            v0 = *(const float4*)&W[(i0 + CC + ssc) * NN + 4 * ssq0];
            v1 = *(const float4*)&W[(i0 + CC + ssc) * NN + 4 * (ssq0 + 8)];
        }
        __syncthreads();                   // zS, wDT visible
        // reduce 8 split-K partials -> zR
        #pragma unroll
        for (int t = 0; t < 2; t++) {
            int idx = tid + t * NTHREADS;
            int k = idx & 63, r = idx >> 6;
            float s = zS[r * ZR + k];
            #pragma unroll
            for (int s8 = 1; s8 < 8; s8++)
                s += zS[(s8 * BR + r) * ZR + k];
            zR[r * ZR + k] = s;
        }
        __syncthreads();                   // zR visible

        // ---- phase 2: triangle, one warp per batch row, no block syncs ----
        {
            const int r  = wrp;
            const int k0 = lane, k1 = lane + 32;
            float a0t = __ldg(&bias[i0 + k0]) + zR[r * ZR + k0];
            float a1t = __ldg(&bias[i0 + k1]) + zR[r * ZR + k1];
            float o0 = 0.f, o1 = 0.f;
            #pragma unroll 4
            for (int j = 0; j < CC; j++) {
                float w0 = wDT[j * WDR + k0];
                float w1 = wDT[j * WDR + k1];
                float zj = __shfl_sync(0xffffffffu, (j < 32) ? a0t : a1t, j & 31);
                float t5 = fminf(fmaxf(5.0f * zj, -60.0f), 60.0f);
                float o  = __fdividef(1.0f, 1.0f + __expf(-t5));
                if (j == k0) o0 = o;
                if (j == k1) o1 = o;
                if (k0 > j) a0t = fmaf(w0, o, a0t);
                if (k1 > j) a1t = fmaf(w1, o, a1t);
            }
            outS[r * SO + g0 + k0] = o0;
            outS[r * SO + g0 + k1] = o1;
        }
        // next chunk's first __syncthreads orders new activations vs readers
    }

    __syncthreads();
    // ---- write output: last NOUT columns ----
    for (int i = tid; i < BR * (NOUT / 4); i += NTHREADS) {
        int r = i >> 6, q = i & 63;
        *(float4*)&out[(row0 + r) * NOUT + 4 * q] =
            *(const float4*)&outS[r * SO + (NN - NOUT) + 4 * q];
    }
}

extern "C" void kernel_launch(void* const* d_in, const int* in_sizes, int n_in,
                              void* d_out, int out_size) {
    const float* x    = (const float*)d_in[0];
    const float* W    = (const float*)d_in[1];
    const float* bias = (const float*)d_in[2];
    float* out        = (float*)d_out;
    (void)in_sizes; (void)n_in; (void)out_size;

    cudaFuncSetAttribute(neat_ff_kernel,
                         cudaFuncAttributeMaxDynamicSharedMemorySize,
                         SMEM_BYTES);
    neat_ff_kernel<<<4096 / BR, NTHREADS, SMEM_BYTES>>>(x, W, bias, out);
}